// round 9
// baseline (speedup 1.0000x reference)
#include <cuda_runtime.h>
#include <cuda_fp16.h>
#include <cstdint>

#define IN_F 256
#define OUT_F 128
#define MAX_NODES 100000
#define BM 128
#define BN 128
#define BK 32
#define NSTAGE 3

__device__ __half g_hh[(size_t)MAX_NODES * OUT_F];
__device__ unsigned g_wt[IN_F * OUT_F];   // weight [k][n], pre-converted tf32-rna bits

__device__ __forceinline__ uint32_t f2tf32u(float x) {
    uint32_t o;
    asm("cvt.rna.tf32.f32 %0, %1;" : "=r"(o) : "f"(x));
    return o;
}

__device__ __forceinline__ void mma_tf32(float* c, const uint32_t* a,
                                         uint32_t b0, uint32_t b1) {
    asm volatile(
        "mma.sync.aligned.m16n8k8.row.col.f32.tf32.tf32.f32 "
        "{%0,%1,%2,%3}, {%4,%5,%6,%7}, {%8,%9}, {%0,%1,%2,%3};\n"
        : "+f"(c[0]), "+f"(c[1]), "+f"(c[2]), "+f"(c[3])
        : "r"(a[0]), "r"(a[1]), "r"(a[2]), "r"(a[3]), "r"(b0), "r"(b1));
}

__device__ __forceinline__ void cp_async16(void* smem_dst, const void* gsrc, int src_bytes) {
    uint32_t daddr = (uint32_t)__cvta_generic_to_shared(smem_dst);
    asm volatile("cp.async.ca.shared.global [%0], [%1], 16, %2;\n"
                 :: "r"(daddr), "l"(gsrc), "r"(src_bytes));
}
__device__ __forceinline__ void cp_commit() {
    asm volatile("cp.async.commit_group;\n" ::: "memory");
}
template <int N>
__device__ __forceinline__ void cp_wait() {
    asm volatile("cp.async.wait_group %0;\n" :: "n"(N) : "memory");
}

// ---------------------------------------------------------------------------
// prep: convert weight to tf32 bits once (removes B cvt from GEMM inner loop)
// ---------------------------------------------------------------------------
__global__ void prep_w_kernel(const float* __restrict__ W) {
    int i = threadIdx.x + blockIdx.x * blockDim.x;
    if (i < IN_F * OUT_F) g_wt[i] = f2tf32u(W[i]);
}

// ---------------------------------------------------------------------------
// GEMM: h = inputs @ weight via tf32 mma.sync, 3-stage cp.async pipeline.
// 256 threads = 8 warps (4M x 2N); warp tile 32x64 (2x8 m16n8k8 per k8).
// ---------------------------------------------------------------------------
__global__ __launch_bounds__(256, 2) void gemm_tf32_kernel(
    const float* __restrict__ A,   // [M, 256] fp32
    float* __restrict__ C,         // [M, 128]
    int M)
{
    __shared__ float As[NSTAGE][BM][BK + 4];       // raw fp32; cvt at frag load
    __shared__ unsigned Bs[NSTAGE][BK][BN + 8];    // tf32 bits (pre-converted)

    const int tid = threadIdx.x;
    const int wid = tid >> 5;
    const int lane = tid & 31;
    const int g = lane >> 2;
    const int t4 = lane & 3;
    const int warp_m = wid & 3;
    const int warp_n = wid >> 2;
    const int row0 = blockIdx.x * BM;

    float c[2][8][4];
#pragma unroll
    for (int mt = 0; mt < 2; mt++)
#pragma unroll
        for (int nt = 0; nt < 8; nt++)
#pragma unroll
            for (int i = 0; i < 4; i++) c[mt][nt][i] = 0.0f;

    const int NITER = IN_F / BK;  // 8

    auto prefetch = [&](int kt) {
        const int buf = kt % NSTAGE;
        const int k0 = kt * BK;
#pragma unroll
        for (int t = 0; t < 4; t++) {
            int idx = tid + t * 256;
            int ar = idx >> 3;             // 0..127
            int ac = idx & 7;              // float4 col 0..7
            int grow = row0 + ar;
            int ok = (grow < M) ? 16 : 0;
            int gc = (grow < M) ? grow : 0;
            cp_async16(&As[buf][ar][ac * 4],
                       A + (size_t)gc * IN_F + k0 + ac * 4, ok);
        }
#pragma unroll
        for (int t = 0; t < 4; t++) {
            int idx = tid + t * 256;
            int br = idx >> 5;             // k 0..31
            int bc = idx & 31;             // 16B col 0..31
            cp_async16(&Bs[buf][br][bc * 4],
                       g_wt + (size_t)(k0 + br) * OUT_F + bc * 4, 16);
        }
        cp_commit();
    };

    prefetch(0);
    prefetch(1);

    for (int kt = 0; kt < NITER; kt++) {
        const int buf = kt % NSTAGE;
        cp_wait<1>();
        __syncthreads();

#pragma unroll
        for (int k8 = 0; k8 < 4; k8++) {
            const int k = k8 * 8;
            uint32_t afr[2][4];
#pragma unroll
            for (int mt = 0; mt < 2; mt++) {
                int rb = warp_m * 32 + mt * 16;
                afr[mt][0] = f2tf32u(As[buf][rb + g][k + t4]);
                afr[mt][1] = f2tf32u(As[buf][rb + g + 8][k + t4]);
                afr[mt][2] = f2tf32u(As[buf][rb + g][k + t4 + 4]);
                afr[mt][3] = f2tf32u(As[buf][rb + g + 8][k + t4 + 4]);
            }
#pragma unroll
            for (int nt = 0; nt < 8; nt++) {
                int nb = warp_n * 64 + nt * 8 + g;
                uint32_t b0 = Bs[buf][k + t4][nb];
                uint32_t b1 = Bs[buf][k + t4 + 4][nb];
                mma_tf32(c[0][nt], afr[0], b0, b1);
                mma_tf32(c[1][nt], afr[1], b0, b1);
            }
        }
        __syncthreads();     // all warps done reading buf kt
        if (kt + 2 < NITER)
            prefetch(kt + 2);   // overwrites buf (kt-1)%3: safe after the sync
    }

    // Epilogue: fp32 to C, fp16 to g_hh.
#pragma unroll
    for (int mt = 0; mt < 2; mt++) {
#pragma unroll
        for (int half = 0; half < 2; half++) {
            int row = row0 + warp_m * 32 + mt * 16 + g + half * 8;
            if (row < M) {
#pragma unroll
                for (int nt = 0; nt < 8; nt++) {
                    int col = warp_n * 64 + nt * 8 + 2 * t4;
                    float x = c[mt][nt][half * 2];
                    float y = c[mt][nt][half * 2 + 1];
                    *reinterpret_cast<float2*>(C + (size_t)row * OUT_F + col) =
                        make_float2(x, y);
                    __half2 hv = __floats2half2_rn(x, y);
                    *reinterpret_cast<__half2*>(g_hh + (size_t)row * OUT_F + col) = hv;
                }
            }
        }
    }
}

// ---------------------------------------------------------------------------
// Edge kernel (unchanged from R7: 76us, at LTS cap): 16 lanes/edge, 2 edges
// per slot-iteration (MLP=4). fp16 gather, fp32 math.
// ---------------------------------------------------------------------------
__device__ __forceinline__ float2 h2f(unsigned w) {
    __half2 b = *reinterpret_cast<__half2*>(&w);
    return __half22float2(b);
}

__device__ __forceinline__ float edge_dot(uint4 hu, uint4 hv,
                                          float4 a0, float4 a1) {
    float2 u0 = h2f(hu.x), u1 = h2f(hu.y), u2 = h2f(hu.z), u3 = h2f(hu.w);
    float2 v0 = h2f(hv.x), v1 = h2f(hv.y), v2 = h2f(hv.z), v3 = h2f(hv.w);
    return fabsf(u0.x - v0.x) * a0.x
         + fabsf(u0.y - v0.y) * a0.y
         + fabsf(u1.x - v1.x) * a0.z
         + fabsf(u1.y - v1.y) * a0.w
         + fabsf(u2.x - v2.x) * a1.x
         + fabsf(u2.y - v2.y) * a1.y
         + fabsf(u3.x - v3.x) * a1.z
         + fabsf(u3.y - v3.y) * a1.w;
}

__global__ __launch_bounds__(256) void edge_kernel(
    const int* __restrict__ edge,         // [2,E] int32
    const float* __restrict__ a,          // [128]
    float* __restrict__ ew,               // [E]
    int E)
{
    const int lane = threadIdx.x & 31;
    const int half_id = lane >> 4;
    const int l16 = lane & 15;

    const float4 a0 = *(reinterpret_cast<const float4*>(a) + l16 * 2);
    const float4 a1 = *(reinterpret_cast<const float4*>(a) + l16 * 2 + 1);

    const int warps_total = (gridDim.x * blockDim.x) >> 5;
    const int warp = (blockIdx.x * blockDim.x + threadIdx.x) >> 5;
    const int stride = warps_total * 2;

    for (int e = warp * 2 + half_id; e < E; e += 2 * stride) {
        const int e2 = e + stride;
        const bool has2 = (e2 < E);

        int u1 = edge[e];
        int v1 = edge[(size_t)E + e];
        int u2 = has2 ? edge[e2] : u1;
        int v2 = has2 ? edge[(size_t)E + e2] : v1;

        uint4 hu1 = *(reinterpret_cast<const uint4*>(g_hh + (size_t)u1 * OUT_F) + l16);
        uint4 hv1 = *(reinterpret_cast<const uint4*>(g_hh + (size_t)v1 * OUT_F) + l16);
        uint4 hu2 = *(reinterpret_cast<const uint4*>(g_hh + (size_t)u2 * OUT_F) + l16);
        uint4 hv2 = *(reinterpret_cast<const uint4*>(g_hh + (size_t)v2 * OUT_F) + l16);

        float s1 = edge_dot(hu1, hv1, a0, a1);
        float s2 = edge_dot(hu2, hv2, a0, a1);

#pragma unroll
        for (int off = 8; off > 0; off >>= 1) {
            s1 += __shfl_down_sync(0xFFFFFFFFu, s1, off, 16);
            s2 += __shfl_down_sync(0xFFFFFFFFu, s2, off, 16);
        }

        if (l16 == 0) {
            ew[e] = fmaxf(s1, 0.0f);
            if (has2) ew[e2] = fmaxf(s2, 0.0f);
        }
    }
}

extern "C" void kernel_launch(void* const* d_in, const int* in_sizes, int n_in,
                              void* d_out, int out_size)
{
    const float* inputs = (const float*)d_in[0];
    const int* edge     = (const int*)d_in[1];
    const float* weight = (const float*)d_in[2];
    const float* a      = (const float*)d_in[3];

    int M = in_sizes[0] / IN_F;        // 100000
    int E = in_sizes[1] / 2;           // 1600000

    float* h  = (float*)d_out;                       // [M,128]
    float* ew = (float*)d_out + (size_t)M * OUT_F;   // [E]

    prep_w_kernel<<<(IN_F * OUT_F + 255) / 256, 256>>>(weight);

    int gemm_blocks = (M + BM - 1) / BM;             // 782
    gemm_tf32_kernel<<<gemm_blocks, 256>>>(inputs, h, M);

    edge_kernel<<<4096, 256>>>(edge, a, ew, E);
}

// round 10
// speedup vs baseline: 1.2058x; 1.2058x over previous
#include <cuda_runtime.h>
#include <cuda_fp16.h>
#include <cstdint>

#define IN_F 256
#define OUT_F 128
#define MAX_NODES 100000
#define BM 128
#define BN 128
#define BK 32

__device__ __half g_hh[(size_t)MAX_NODES * OUT_F];

__device__ __forceinline__ uint32_t f2tf32u(float x) {
    uint32_t o;
    asm("cvt.rna.tf32.f32 %0, %1;" : "=r"(o) : "f"(x));
    return o;
}

__device__ __forceinline__ void mma_tf32(float* c, const uint32_t* a,
                                         uint32_t b0, uint32_t b1) {
    asm volatile(
        "mma.sync.aligned.m16n8k8.row.col.f32.tf32.tf32.f32 "
        "{%0,%1,%2,%3}, {%4,%5,%6,%7}, {%8,%9}, {%0,%1,%2,%3};\n"
        : "+f"(c[0]), "+f"(c[1]), "+f"(c[2]), "+f"(c[3])
        : "r"(a[0]), "r"(a[1]), "r"(a[2]), "r"(a[3]), "r"(b0), "r"(b1));
}

__device__ __forceinline__ void cp_async16(void* smem_dst, const void* gsrc, int src_bytes) {
    uint32_t daddr = (uint32_t)__cvta_generic_to_shared(smem_dst);
    asm volatile("cp.async.ca.shared.global [%0], [%1], 16, %2;\n"
                 :: "r"(daddr), "l"(gsrc), "r"(src_bytes));
}
__device__ __forceinline__ void cp_commit() {
    asm volatile("cp.async.commit_group;\n" ::: "memory");
}
template <int N>
__device__ __forceinline__ void cp_wait() {
    asm volatile("cp.async.wait_group %0;\n" :: "n"(N) : "memory");
}

// ---------------------------------------------------------------------------
// GEMM (exact R7 form, 63us): tf32 mma.sync, 2-stage cp.async pipeline.
// 256 threads = 8 warps (4M x 2N); warp tile 32x64 (2x8 m16n8k8 per k8).
// ---------------------------------------------------------------------------
__global__ __launch_bounds__(256) void gemm_tf32_kernel(
    const float* __restrict__ A,   // [M, 256]
    const float* __restrict__ Bw,  // [256, 128]
    float* __restrict__ C,         // [M, 128]
    int M)
{
    __shared__ float As[2][BM][BK + 4];
    __shared__ float Bs[2][BK][BN + 8];

    const int tid = threadIdx.x;
    const int wid = tid >> 5;
    const int lane = tid & 31;
    const int g = lane >> 2;
    const int t4 = lane & 3;
    const int warp_m = wid & 3;
    const int warp_n = wid >> 2;
    const int row0 = blockIdx.x * BM;

    float c[2][8][4];
#pragma unroll
    for (int mt = 0; mt < 2; mt++)
#pragma unroll
        for (int nt = 0; nt < 8; nt++)
#pragma unroll
            for (int i = 0; i < 4; i++) c[mt][nt][i] = 0.0f;

    const int NITER = IN_F / BK;  // 8

    auto prefetch = [&](int kt, int buf) {
        const int k0 = kt * BK;
#pragma unroll
        for (int t = 0; t < 4; t++) {
            int idx = tid + t * 256;
            int ar = idx >> 3;
            int ac = idx & 7;
            int grow = row0 + ar;
            int ok = (grow < M) ? 16 : 0;
            int gc = (grow < M) ? grow : 0;
            cp_async16(&As[buf][ar][ac * 4],
                       A + (size_t)gc * IN_F + k0 + ac * 4, ok);
        }
#pragma unroll
        for (int t = 0; t < 4; t++) {
            int idx = tid + t * 256;
            int br = idx >> 5;
            int bc = idx & 31;
            cp_async16(&Bs[buf][br][bc * 4],
                       Bw + (size_t)(k0 + br) * OUT_F + bc * 4, 16);
        }
        cp_commit();
    };

    prefetch(0, 0);

    for (int kt = 0; kt < NITER; kt++) {
        const int buf = kt & 1;
        if (kt + 1 < NITER) {
            prefetch(kt + 1, (kt + 1) & 1);
            cp_wait<1>();
        } else {
            cp_wait<0>();
        }
        __syncthreads();

#pragma unroll
        for (int k8 = 0; k8 < 4; k8++) {
            const int k = k8 * 8;
            uint32_t afr[2][4];
#pragma unroll
            for (int mt = 0; mt < 2; mt++) {
                int rb = warp_m * 32 + mt * 16;
                afr[mt][0] = f2tf32u(As[buf][rb + g][k + t4]);
                afr[mt][1] = f2tf32u(As[buf][rb + g + 8][k + t4]);
                afr[mt][2] = f2tf32u(As[buf][rb + g][k + t4 + 4]);
                afr[mt][3] = f2tf32u(As[buf][rb + g + 8][k + t4 + 4]);
            }
#pragma unroll
            for (int nt = 0; nt < 8; nt++) {
                int nb = warp_n * 64 + nt * 8 + g;
                uint32_t b0 = f2tf32u(Bs[buf][k + t4][nb]);
                uint32_t b1 = f2tf32u(Bs[buf][k + t4 + 4][nb]);
                mma_tf32(c[0][nt], afr[0], b0, b1);
                mma_tf32(c[1][nt], afr[1], b0, b1);
            }
        }
        __syncthreads();
    }

    // Epilogue: fp32 to C, fp16 to g_hh.
#pragma unroll
    for (int mt = 0; mt < 2; mt++) {
#pragma unroll
        for (int half = 0; half < 2; half++) {
            int row = row0 + warp_m * 32 + mt * 16 + g + half * 8;
            if (row < M) {
#pragma unroll
                for (int nt = 0; nt < 8; nt++) {
                    int col = warp_n * 64 + nt * 8 + 2 * t4;
                    float x = c[mt][nt][half * 2];
                    float y = c[mt][nt][half * 2 + 1];
                    *reinterpret_cast<float2*>(C + (size_t)row * OUT_F + col) =
                        make_float2(x, y);
                    __half2 hv = __floats2half2_rn(x, y);
                    *reinterpret_cast<__half2*>(g_hh + (size_t)row * OUT_F + col) = hv;
                }
            }
        }
    }
}

// ---------------------------------------------------------------------------
// Edge kernel: 16 lanes per edge, 3 edges per slot per iteration (MLP=6).
// fp16 gather, fp32 math.
// ---------------------------------------------------------------------------
__device__ __forceinline__ float2 h2f(unsigned w) {
    __half2 b = *reinterpret_cast<__half2*>(&w);
    return __half22float2(b);
}

__device__ __forceinline__ float edge_dot(uint4 hu, uint4 hv,
                                          float4 a0, float4 a1) {
    float2 u0 = h2f(hu.x), u1 = h2f(hu.y), u2 = h2f(hu.z), u3 = h2f(hu.w);
    float2 v0 = h2f(hv.x), v1 = h2f(hv.y), v2 = h2f(hv.z), v3 = h2f(hv.w);
    return fabsf(u0.x - v0.x) * a0.x
         + fabsf(u0.y - v0.y) * a0.y
         + fabsf(u1.x - v1.x) * a0.z
         + fabsf(u1.y - v1.y) * a0.w
         + fabsf(u2.x - v2.x) * a1.x
         + fabsf(u2.y - v2.y) * a1.y
         + fabsf(u3.x - v3.x) * a1.z
         + fabsf(u3.y - v3.y) * a1.w;
}

__global__ __launch_bounds__(256) void edge_kernel(
    const int* __restrict__ edge,         // [2,E] int32
    const float* __restrict__ a,          // [128]
    float* __restrict__ ew,               // [E]
    int E)
{
    const int lane = threadIdx.x & 31;
    const int half_id = lane >> 4;
    const int l16 = lane & 15;

    const float4 a0 = *(reinterpret_cast<const float4*>(a) + l16 * 2);
    const float4 a1 = *(reinterpret_cast<const float4*>(a) + l16 * 2 + 1);

    const int warps_total = (gridDim.x * blockDim.x) >> 5;
    const int warp = (blockIdx.x * blockDim.x + threadIdx.x) >> 5;
    const int stride = warps_total * 2;   // edge slots per grid pass

    for (int e = warp * 2 + half_id; e < E; e += 3 * stride) {
        const int e2 = e + stride;
        const int e3 = e + 2 * stride;
        const bool has2 = (e2 < E);
        const bool has3 = (e3 < E);

        int u1 = edge[e];
        int v1 = edge[(size_t)E + e];
        int u2 = has2 ? edge[e2] : u1;
        int v2 = has2 ? edge[(size_t)E + e2] : v1;
        int u3 = has3 ? edge[e3] : u1;
        int v3 = has3 ? edge[(size_t)E + e3] : v1;

        // Issue all 6 gathers before computing (MLP=6)
        uint4 hu1 = *(reinterpret_cast<const uint4*>(g_hh + (size_t)u1 * OUT_F) + l16);
        uint4 hv1 = *(reinterpret_cast<const uint4*>(g_hh + (size_t)v1 * OUT_F) + l16);
        uint4 hu2 = *(reinterpret_cast<const uint4*>(g_hh + (size_t)u2 * OUT_F) + l16);
        uint4 hv2 = *(reinterpret_cast<const uint4*>(g_hh + (size_t)v2 * OUT_F) + l16);
        uint4 hu3 = *(reinterpret_cast<const uint4*>(g_hh + (size_t)u3 * OUT_F) + l16);
        uint4 hv3 = *(reinterpret_cast<const uint4*>(g_hh + (size_t)v3 * OUT_F) + l16);

        float s1 = edge_dot(hu1, hv1, a0, a1);
        float s2 = edge_dot(hu2, hv2, a0, a1);
        float s3 = edge_dot(hu3, hv3, a0, a1);

#pragma unroll
        for (int off = 8; off > 0; off >>= 1) {
            s1 += __shfl_down_sync(0xFFFFFFFFu, s1, off, 16);
            s2 += __shfl_down_sync(0xFFFFFFFFu, s2, off, 16);
            s3 += __shfl_down_sync(0xFFFFFFFFu, s3, off, 16);
        }

        if (l16 == 0) {
            ew[e] = fmaxf(s1, 0.0f);
            if (has2) ew[e2] = fmaxf(s2, 0.0f);
            if (has3) ew[e3] = fmaxf(s3, 0.0f);
        }
    }
}

extern "C" void kernel_launch(void* const* d_in, const int* in_sizes, int n_in,
                              void* d_out, int out_size)
{
    const float* inputs = (const float*)d_in[0];
    const int* edge     = (const int*)d_in[1];
    const float* weight = (const float*)d_in[2];
    const float* a      = (const float*)d_in[3];

    int M = in_sizes[0] / IN_F;        // 100000
    int E = in_sizes[1] / 2;           // 1600000

    float* h  = (float*)d_out;                       // [M,128]
    float* ew = (float*)d_out + (size_t)M * OUT_F;   // [E]

    int gemm_blocks = (M + BM - 1) / BM;             // 782
    gemm_tf32_kernel<<<gemm_blocks, 256>>>(inputs, weight, h, M);

    edge_kernel<<<4096, 256>>>(edge, a, ew, E);
}